// round 5
// baseline (speedup 1.0000x reference)
#include <cuda_runtime.h>
#include <cstdint>

#define DEVI __device__ __forceinline__

namespace {
constexpr int Bb    = 4;
constexpr int Nn    = 2048;
constexpr int HEADS = 16;
constexpr int DH    = 64;
constexpr int INNER = 1024;
constexpr int MROWS = Bb * Nn;   // 8192
constexpr int ATTN_SMEM_FLOATS = 64*68 + 64*68 + 64*72 + 4*16*68; // Qs, Ks, Vs, Ps
constexpr int ATTN_SMEM_BYTES  = ATTN_SMEM_FLOATS * 4;            // 70656
}

// ---- scratch (device globals: allocation-free) ----
__device__ float g_Q [(size_t)Bb*HEADS*Nn*DH];
__device__ float g_K [(size_t)Bb*HEADS*Nn*DH];
__device__ float g_V [(size_t)Bb*HEADS*Nn*DH];
__device__ float g_AO[(size_t)MROWS*INNER];

DEVI uint32_t f2tf(float x) {
    uint32_t r;
    asm("cvt.rna.tf32.f32 %0, %1;" : "=r"(r) : "f"(x));
    return r;
}

DEVI void mma8(float* c, const uint32_t* a, uint32_t b0, uint32_t b1) {
    asm volatile(
        "mma.sync.aligned.m16n8k8.row.col.f32.tf32.tf32.f32 "
        "{%0,%1,%2,%3}, {%4,%5,%6,%7}, {%8,%9}, {%0,%1,%2,%3};\n"
        : "+f"(c[0]), "+f"(c[1]), "+f"(c[2]), "+f"(c[3])
        : "r"(a[0]), "r"(a[1]), "r"(a[2]), "r"(a[3]), "r"(b0), "r"(b1));
}

// ============================================================================
// GEMM: C[M,N] = A[M,K] @ W[K,N]   (A row-major, W row-major)
// MODE 0: A = x, scatter into g_Q/g_K/g_V head layout
// MODE 1: A = g_AO, out = dout + bias
// Block tile 128x128, BK=16, 8 warps (4x2), warp tile 32x64, tf32 m16n8k8.
// ============================================================================
template <int MODE>
__global__ void __launch_bounds__(256)
gemm_k(const float* __restrict__ A, const float* __restrict__ W,
       int M, int N, int K,
       const float* __restrict__ bias, float* __restrict__ dout)
{
    __shared__ float As[128][20];   // [m][k], stride 20 (conflict-free A frags)
    __shared__ float Bs[16][136];   // [k][n], stride 136 (conflict-free B frags)

    const int tid  = threadIdx.x;
    const int lane = tid & 31;
    const int g    = lane >> 2;     // groupID
    const int tg   = lane & 3;      // thread-in-group
    const int wid  = tid >> 5;
    const int wm   = wid >> 1;      // 0..3
    const int wn   = wid & 1;       // 0..1
    const int bm   = blockIdx.y * 128;
    const int bn   = blockIdx.x * 128;

    const float* Ap = (MODE == 1) ? g_AO : A;

    float acc[2][8][4];
#pragma unroll
    for (int i = 0; i < 2; i++)
#pragma unroll
        for (int j = 0; j < 8; j++)
#pragma unroll
            for (int q = 0; q < 4; q++) acc[i][j][q] = 0.f;

    const int nkt = K >> 4;
    for (int kt = 0; kt < nkt; kt++) {
        // load A tile: 128x16 = 512 float4, 2 per thread
#pragma unroll
        for (int i = 0; i < 2; i++) {
            int idx = tid + i * 256;
            int row = idx >> 2, k4 = (idx & 3) << 2;
            float4 v = *reinterpret_cast<const float4*>(
                &Ap[(size_t)(bm + row) * K + kt * 16 + k4]);
            *reinterpret_cast<float4*>(&As[row][k4]) = v;
        }
        // load B tile: 16x128 = 512 float4
#pragma unroll
        for (int i = 0; i < 2; i++) {
            int idx = tid + i * 256;
            int row = idx >> 5, n4 = (idx & 31) << 2;
            float4 v = *reinterpret_cast<const float4*>(
                &W[(size_t)(kt * 16 + row) * N + bn + n4]);
            *reinterpret_cast<float4*>(&Bs[row][n4]) = v;
        }
        __syncthreads();

#pragma unroll
        for (int kk = 0; kk < 16; kk += 8) {
            uint32_t a[2][4];
#pragma unroll
            for (int mi = 0; mi < 2; mi++) {
                int mr = wm * 32 + mi * 16;
                a[mi][0] = f2tf(As[mr + g    ][kk + tg    ]);
                a[mi][1] = f2tf(As[mr + g + 8][kk + tg    ]);
                a[mi][2] = f2tf(As[mr + g    ][kk + tg + 4]);
                a[mi][3] = f2tf(As[mr + g + 8][kk + tg + 4]);
            }
#pragma unroll
            for (int ni = 0; ni < 8; ni++) {
                int nc = wn * 64 + ni * 8 + g;
                uint32_t b0 = f2tf(Bs[kk + tg    ][nc]);
                uint32_t b1 = f2tf(Bs[kk + tg + 4][nc]);
                mma8(acc[0][ni], a[0], b0, b1);
                mma8(acc[1][ni], a[1], b0, b1);
            }
        }
        __syncthreads();
    }

    // epilogue
#pragma unroll
    for (int mi = 0; mi < 2; mi++) {
#pragma unroll
        for (int ni = 0; ni < 8; ni++) {
#pragma unroll
            for (int q = 0; q < 4; q++) {
                int r = bm + wm * 32 + mi * 16 + g + ((q >= 2) ? 8 : 0);
                int c = bn + wn * 64 + ni * 8 + tg * 2 + (q & 1);
                float v = acc[mi][ni][q];
                if (MODE == 0) {
                    int b = r >> 11, n = r & 2047;
                    int which = c >> 10, cc = c & 1023;
                    int h = cc >> 6, d = cc & 63;
                    float* dst = (which == 0) ? g_Q : ((which == 1) ? g_K : g_V);
                    dst[((((size_t)b * HEADS + h) * Nn) + n) * DH + d] = v;
                } else {
                    dout[(size_t)r * N + c] = v + bias[c];
                }
            }
        }
    }
}

// ============================================================================
// Flash attention: per block = one (b,h) x 64 query rows. 4 warps x 16 rows.
// Bc = 64, online softmax, tf32 MMAs for QK^T and PV.
// ============================================================================
__global__ void __launch_bounds__(128)
attn_k()
{
    extern __shared__ float sm[];
    float* Qs = sm;                  // [64][68]
    float* Ks = Qs + 64 * 68;        // [64][68]
    float* Vs = Ks + 64 * 68;        // [64][72]
    float* Ps = Vs + 64 * 72;        // [4][16][68]

    const int tid  = threadIdx.x;
    const int lane = tid & 31;
    const int w    = tid >> 5;
    const int g    = lane >> 2;
    const int tg   = lane & 3;
    const int bh   = blockIdx.y;     // b*16 + h
    const int qt   = blockIdx.x;     // 0..31

    const size_t base = (size_t)bh * Nn * DH;
    const float* Qp = g_Q + base + (size_t)qt * 64 * DH;
    const float* Kp = g_K + base;
    const float* Vp = g_V + base;

    // load Q tile, fold in softmax scale 1/sqrt(64) = 0.125
#pragma unroll
    for (int i = 0; i < 8; i++) {
        int idx = tid + i * 128;             // 0..1023
        int row = idx >> 4, c4 = (idx & 15) << 2;
        float4 v = *reinterpret_cast<const float4*>(&Qp[row * 64 + c4]);
        v.x *= 0.125f; v.y *= 0.125f; v.z *= 0.125f; v.w *= 0.125f;
        *reinterpret_cast<float4*>(&Qs[row * 68 + c4]) = v;
    }

    float m_i[2] = {-1e30f, -1e30f};
    float l_i[2] = {0.f, 0.f};
    float o[8][4];
#pragma unroll
    for (int i = 0; i < 8; i++)
#pragma unroll
        for (int q = 0; q < 4; q++) o[i][q] = 0.f;

    float* Pw = Ps + w * 16 * 68;
    const int mr = w * 16;

    for (int jt = 0; jt < 32; jt++) {
        __syncthreads();
        // load K and V tiles (64x64 each)
#pragma unroll
        for (int i = 0; i < 8; i++) {
            int idx = tid + i * 128;
            int row = idx >> 4, c4 = (idx & 15) << 2;
            float4 kv = *reinterpret_cast<const float4*>(&Kp[(jt * 64 + row) * 64 + c4]);
            *reinterpret_cast<float4*>(&Ks[row * 68 + c4]) = kv;
            float4 vv = *reinterpret_cast<const float4*>(&Vp[(jt * 64 + row) * 64 + c4]);
            *reinterpret_cast<float4*>(&Vs[row * 72 + c4]) = vv;
        }
        __syncthreads();

        // ---- S = Q @ K^T : 16x64, k=64 ----
        float s[8][4];
#pragma unroll
        for (int i = 0; i < 8; i++)
#pragma unroll
            for (int q = 0; q < 4; q++) s[i][q] = 0.f;

#pragma unroll
        for (int kk = 0; kk < 8; kk++) {
            uint32_t a[4];
            a[0] = f2tf(Qs[(mr + g    ) * 68 + kk * 8 + tg    ]);
            a[1] = f2tf(Qs[(mr + g + 8) * 68 + kk * 8 + tg    ]);
            a[2] = f2tf(Qs[(mr + g    ) * 68 + kk * 8 + tg + 4]);
            a[3] = f2tf(Qs[(mr + g + 8) * 68 + kk * 8 + tg + 4]);
#pragma unroll
            for (int ni = 0; ni < 8; ni++) {
                uint32_t b0 = f2tf(Ks[(ni * 8 + g) * 68 + kk * 8 + tg    ]);
                uint32_t b1 = f2tf(Ks[(ni * 8 + g) * 68 + kk * 8 + tg + 4]);
                mma8(s[ni], a, b0, b1);
            }
        }

        // ---- online softmax ----
        float mx0 = -1e30f, mx1 = -1e30f;
#pragma unroll
        for (int ni = 0; ni < 8; ni++) {
            mx0 = fmaxf(mx0, fmaxf(s[ni][0], s[ni][1]));
            mx1 = fmaxf(mx1, fmaxf(s[ni][2], s[ni][3]));
        }
#pragma unroll
        for (int off = 1; off < 4; off <<= 1) {
            mx0 = fmaxf(mx0, __shfl_xor_sync(0xffffffffu, mx0, off));
            mx1 = fmaxf(mx1, __shfl_xor_sync(0xffffffffu, mx1, off));
        }
        float mn0 = fmaxf(m_i[0], mx0);
        float mn1 = fmaxf(m_i[1], mx1);
        float al0 = __expf(m_i[0] - mn0);
        float al1 = __expf(m_i[1] - mn1);
        l_i[0] *= al0; l_i[1] *= al1;
#pragma unroll
        for (int ni = 0; ni < 8; ni++) {
            o[ni][0] *= al0; o[ni][1] *= al0;
            o[ni][2] *= al1; o[ni][3] *= al1;
        }
        float rs0 = 0.f, rs1 = 0.f;
#pragma unroll
        for (int ni = 0; ni < 8; ni++) {
            s[ni][0] = __expf(s[ni][0] - mn0);
            s[ni][1] = __expf(s[ni][1] - mn0);
            s[ni][2] = __expf(s[ni][2] - mn1);
            s[ni][3] = __expf(s[ni][3] - mn1);
            rs0 += s[ni][0] + s[ni][1];
            rs1 += s[ni][2] + s[ni][3];
        }
#pragma unroll
        for (int off = 1; off < 4; off <<= 1) {
            rs0 += __shfl_xor_sync(0xffffffffu, rs0, off);
            rs1 += __shfl_xor_sync(0xffffffffu, rs1, off);
        }
        l_i[0] += rs0; l_i[1] += rs1;
        m_i[0] = mn0;  m_i[1] = mn1;

        // ---- P -> smem (C-layout to A-layout fixup), per-warp buffer ----
#pragma unroll
        for (int ni = 0; ni < 8; ni++) {
            Pw[(g    ) * 68 + ni * 8 + tg * 2    ] = s[ni][0];
            Pw[(g    ) * 68 + ni * 8 + tg * 2 + 1] = s[ni][1];
            Pw[(g + 8) * 68 + ni * 8 + tg * 2    ] = s[ni][2];
            Pw[(g + 8) * 68 + ni * 8 + tg * 2 + 1] = s[ni][3];
        }
        __syncwarp();

        // ---- O += P @ V : 16x64, k=64 ----
#pragma unroll
        for (int kk = 0; kk < 8; kk++) {
            uint32_t a[4];
            a[0] = f2tf(Pw[(g    ) * 68 + kk * 8 + tg    ]);
            a[1] = f2tf(Pw[(g + 8) * 68 + kk * 8 + tg    ]);
            a[2] = f2tf(Pw[(g    ) * 68 + kk * 8 + tg + 4]);
            a[3] = f2tf(Pw[(g + 8) * 68 + kk * 8 + tg + 4]);
#pragma unroll
            for (int ni = 0; ni < 8; ni++) {
                uint32_t b0 = f2tf(Vs[(kk * 8 + tg    ) * 72 + ni * 8 + g]);
                uint32_t b1 = f2tf(Vs[(kk * 8 + tg + 4) * 72 + ni * 8 + g]);
                mma8(o[ni], a, b0, b1);
            }
        }
        __syncwarp();
    }

    // ---- epilogue: normalize and write [B, N, INNER] ----
    float inv0 = 1.f / l_i[0];
    float inv1 = 1.f / l_i[1];
    int b = bh >> 4, h = bh & 15;
#pragma unroll
    for (int ni = 0; ni < 8; ni++) {
#pragma unroll
        for (int q = 0; q < 4; q++) {
            int nrow = qt * 64 + w * 16 + g + ((q >= 2) ? 8 : 0);
            int col  = h * 64 + ni * 8 + tg * 2 + (q & 1);
            float v  = o[ni][q] * ((q >= 2) ? inv1 : inv0);
            g_AO[((size_t)(b * Nn + nrow)) * INNER + col] = v;
        }
    }
}

// ============================================================================
extern "C" void kernel_launch(void* const* d_in, const int* in_sizes, int n_in,
                              void* d_out, int out_size)
{
    const float* x    = (const float*)d_in[0];   // [4,2048,1024]
    const float* wqkv = (const float*)d_in[1];   // [1024,3072]
    const float* wout = (const float*)d_in[2];   // [1024,1024]
    const float* bout = (const float*)d_in[3];   // [1024]
    float* out = (float*)d_out;                  // [4,2048,1024]

    // 1) QKV projection with head scatter
    gemm_k<0><<<dim3(3072 / 128, MROWS / 128), 256>>>(
        x, wqkv, MROWS, 3072, 1024, nullptr, nullptr);

    // 2) flash attention
    cudaFuncSetAttribute(attn_k, cudaFuncAttributeMaxDynamicSharedMemorySize,
                         ATTN_SMEM_BYTES);
    attn_k<<<dim3(Nn / 64, Bb * HEADS), 128, ATTN_SMEM_BYTES>>>();

    // 3) output projection + bias
    gemm_k<1><<<dim3(1024 / 128, MROWS / 128), 256>>>(
        nullptr, wout, MROWS, 1024, 1024, bout, out);
}

// round 9
// speedup vs baseline: 1.1027x; 1.1027x over previous
#include <cuda_runtime.h>
#include <cstdint>

#define DEVI __device__ __forceinline__

namespace {
constexpr int Bb    = 4;
constexpr int Nn    = 2048;
constexpr int HEADS = 16;
constexpr int DH    = 64;
constexpr int INNER = 1024;
constexpr int MROWS = Bb * Nn;   // 8192
// attn smem (uint32 words): Qs 64*68, Ks 2*64*68, Vs 2*64*72, Ps 4*16*68
constexpr int ATTN_SMEM_WORDS = 64*68 + 2*64*68 + 2*64*72 + 4*16*68; // 26624
constexpr int ATTN_SMEM_BYTES = ATTN_SMEM_WORDS * 4;                 // 106496
}

// ---- scratch (device globals: allocation-free) ----
// g_Q/g_K/g_V hold tf32-rounded bits (stored as float); Q pre-scaled by 0.125
__device__ float g_Q [(size_t)Bb*HEADS*Nn*DH];
__device__ float g_K [(size_t)Bb*HEADS*Nn*DH];
__device__ float g_V [(size_t)Bb*HEADS*Nn*DH];
__device__ float g_AO[(size_t)MROWS*INNER];

DEVI uint32_t f2tf(float x) {
    uint32_t r;
    asm("cvt.rna.tf32.f32 %0, %1;" : "=r"(r) : "f"(x));
    return r;
}

DEVI void mma8(float* c, const uint32_t* a, uint32_t b0, uint32_t b1) {
    asm volatile(
        "mma.sync.aligned.m16n8k8.row.col.f32.tf32.tf32.f32 "
        "{%0,%1,%2,%3}, {%4,%5,%6,%7}, {%8,%9}, {%0,%1,%2,%3};\n"
        : "+f"(c[0]), "+f"(c[1]), "+f"(c[2]), "+f"(c[3])
        : "r"(a[0]), "r"(a[1]), "r"(a[2]), "r"(a[3]), "r"(b0), "r"(b1));
}

DEVI uint32_t saddr(const void* p) {
    return (uint32_t)__cvta_generic_to_shared(p);
}
DEVI void cpa16(uint32_t dst, const void* src) {
    asm volatile("cp.async.cg.shared.global [%0], [%1], 16;\n"
                 :: "r"(dst), "l"(src));
}
DEVI void cpa_commit() { asm volatile("cp.async.commit_group;\n"); }
template <int N> DEVI void cpa_wait() {
    asm volatile("cp.async.wait_group %0;\n" :: "n"(N));
}

// ============================================================================
// GEMM: C[M,N] = A[M,K] @ W[K,N]  (both row-major), tf32 m16n8k8.
// Block tile 128x128, BK=16, 8 warps (4x2), warp tile 32x64.
// Double-buffered smem (register-staged); smem holds tf32 bits (cvt hoisted).
// MODE 0: A = x, epilogue scatters tf32-rounded Q(*0.125)/K/V head layout
// MODE 1: A = g_AO, epilogue writes dout + bias (fp32)
// ============================================================================
template <int MODE>
__global__ void __launch_bounds__(256)
gemm_k(const float* __restrict__ A, const float* __restrict__ W,
       int M, int N, int K,
       const float* __restrict__ bias, float* __restrict__ dout)
{
    __shared__ uint32_t As[2][128][20];   // [m][k], pad 20
    __shared__ uint32_t Bs[2][16][136];   // [k][n], pad 136

    const int tid  = threadIdx.x;
    const int lane = tid & 31;
    const int g    = lane >> 2;
    const int tg   = lane & 3;
    const int wid  = tid >> 5;
    const int wm   = wid >> 1;      // 0..3
    const int wn   = wid & 1;       // 0..1
    const int bm   = blockIdx.y * 128;
    const int bn   = blockIdx.x * 128;

    const float* Ap = (MODE == 1) ? g_AO : A;

    // per-thread staging coords (2 float4 each for A and B per k-tile)
    const int arow = tid >> 2, ak4 = (tid & 3) << 2;    // + i*64
    const int brow = tid >> 5, bn4 = (tid & 31) << 2;   // + i*8

    float4 ra[2], rb[2];

    float acc[2][8][4];
#pragma unroll
    for (int i = 0; i < 2; i++)
#pragma unroll
        for (int j = 0; j < 8; j++)
#pragma unroll
            for (int q = 0; q < 4; q++) acc[i][j][q] = 0.f;

    const int nkt = K >> 4;

    // prologue: tile 0
#pragma unroll
    for (int i = 0; i < 2; i++) {
        ra[i] = *reinterpret_cast<const float4*>(
            &Ap[(size_t)(bm + arow + i * 64) * K + ak4]);
        rb[i] = *reinterpret_cast<const float4*>(
            &W[(size_t)(brow + i * 8) * N + bn + bn4]);
    }
#pragma unroll
    for (int i = 0; i < 2; i++) {
        uint32_t* pa = &As[0][arow + i * 64][ak4];
        pa[0] = f2tf(ra[i].x); pa[1] = f2tf(ra[i].y);
        pa[2] = f2tf(ra[i].z); pa[3] = f2tf(ra[i].w);
        uint32_t* pb = &Bs[0][brow + i * 8][bn4];
        pb[0] = f2tf(rb[i].x); pb[1] = f2tf(rb[i].y);
        pb[2] = f2tf(rb[i].z); pb[3] = f2tf(rb[i].w);
    }
    __syncthreads();

    for (int kt = 0; kt < nkt; kt++) {
        const int cur = kt & 1;
        if (kt + 1 < nkt) {
#pragma unroll
            for (int i = 0; i < 2; i++) {
                ra[i] = *reinterpret_cast<const float4*>(
                    &Ap[(size_t)(bm + arow + i * 64) * K + (kt + 1) * 16 + ak4]);
                rb[i] = *reinterpret_cast<const float4*>(
                    &W[(size_t)((kt + 1) * 16 + brow + i * 8) * N + bn + bn4]);
            }
        }

#pragma unroll
        for (int kk = 0; kk < 16; kk += 8) {
            uint32_t a[2][4];
#pragma unroll
            for (int mi = 0; mi < 2; mi++) {
                int mr = wm * 32 + mi * 16;
                a[mi][0] = As[cur][mr + g    ][kk + tg    ];
                a[mi][1] = As[cur][mr + g + 8][kk + tg    ];
                a[mi][2] = As[cur][mr + g    ][kk + tg + 4];
                a[mi][3] = As[cur][mr + g + 8][kk + tg + 4];
            }
#pragma unroll
            for (int ni = 0; ni < 8; ni++) {
                int nc = wn * 64 + ni * 8 + g;
                uint32_t b0 = Bs[cur][kk + tg    ][nc];
                uint32_t b1 = Bs[cur][kk + tg + 4][nc];
                mma8(acc[0][ni], a[0], b0, b1);
                mma8(acc[1][ni], a[1], b0, b1);
            }
        }

        if (kt + 1 < nkt) {
            const int nxt = (kt + 1) & 1;
#pragma unroll
            for (int i = 0; i < 2; i++) {
                uint32_t* pa = &As[nxt][arow + i * 64][ak4];
                pa[0] = f2tf(ra[i].x); pa[1] = f2tf(ra[i].y);
                pa[2] = f2tf(ra[i].z); pa[3] = f2tf(ra[i].w);
                uint32_t* pb = &Bs[nxt][brow + i * 8][bn4];
                pb[0] = f2tf(rb[i].x); pb[1] = f2tf(rb[i].y);
                pb[2] = f2tf(rb[i].z); pb[3] = f2tf(rb[i].w);
            }
        }
        __syncthreads();
    }

    // epilogue
#pragma unroll
    for (int mi = 0; mi < 2; mi++) {
#pragma unroll
        for (int ni = 0; ni < 8; ni++) {
#pragma unroll
            for (int q = 0; q < 4; q++) {
                int r = bm + wm * 32 + mi * 16 + g + ((q >= 2) ? 8 : 0);
                int c = bn + wn * 64 + ni * 8 + tg * 2 + (q & 1);
                float v = acc[mi][ni][q];
                if (MODE == 0) {
                    int b = r >> 11, n = r & 2047;
                    int which = c >> 10, cc = c & 1023;
                    int h = cc >> 6, d = cc & 63;
                    float* dst = (which == 0) ? g_Q : ((which == 1) ? g_K : g_V);
                    if (which == 0) v *= 0.125f;   // fold softmax scale into Q
                    dst[((((size_t)b * HEADS + h) * Nn) + n) * DH + d] =
                        __uint_as_float(f2tf(v));  // pre-round to tf32
                } else {
                    dout[(size_t)r * N + c] = v + bias[c];
                }
            }
        }
    }
}

// ============================================================================
// Flash attention: block = one (b,h) x 64 query rows, 4 warps x 16 rows.
// Q/K/V arrive pre-converted to tf32 bits -> zero cvt in MMA loops.
// K/V double-buffered via cp.async (2 stages).
// ============================================================================
__global__ void __launch_bounds__(128)
attn_k()
{
    extern __shared__ uint32_t smu[];
    uint32_t* Qs = smu;                      // [64][68]
    uint32_t* Ks = Qs + 64 * 68;             // [2][64][68]
    uint32_t* Vs = Ks + 2 * 64 * 68;         // [2][64][72]
    uint32_t* Ps = Vs + 2 * 64 * 72;         // [4][16][68]

    const int tid  = threadIdx.x;
    const int lane = tid & 31;
    const int w    = tid >> 5;
    const int g    = lane >> 2;
    const int tg   = lane & 3;
    const int bh   = blockIdx.y;             // b*16 + h
    const int qt   = blockIdx.x;             // 0..31

    const size_t base = (size_t)bh * Nn * DH;
    const float* Qp = g_Q + base + (size_t)qt * 64 * DH;
    const float* Kp = g_K + base;
    const float* Vp = g_V + base;

    const int lrow = tid >> 4;               // 0..7
    const int lc4  = (tid & 15) << 2;        // 0..60 step 4

    // prefetch tile 0 (K/V) + Q, all in cp.async group 0
#pragma unroll
    for (int i = 0; i < 8; i++) {
        int row = lrow + i * 8;
        cpa16(saddr(&Ks[row * 68 + lc4]), &Kp[row * 64 + lc4]);
        cpa16(saddr(&Vs[row * 72 + lc4]), &Vp[row * 64 + lc4]);
        cpa16(saddr(&Qs[row * 68 + lc4]), &Qp[row * 64 + lc4]);
    }
    cpa_commit();

    float m_i[2] = {-1e30f, -1e30f};
    float l_i[2] = {0.f, 0.f};
    float o[8][4];
#pragma unroll
    for (int i = 0; i < 8; i++)
#pragma unroll
        for (int q = 0; q < 4; q++) o[i][q] = 0.f;

    uint32_t* Pw = Ps + w * 16 * 68;
    const int mr = w * 16;

    for (int jt = 0; jt < 32; jt++) {
        const int st = jt & 1;
        if (jt + 1 < 32) {
            const int ns = st ^ 1;
#pragma unroll
            for (int i = 0; i < 8; i++) {
                int row = lrow + i * 8;
                cpa16(saddr(&Ks[(ns * 64 + row) * 68 + lc4]),
                      &Kp[((jt + 1) * 64 + row) * 64 + lc4]);
                cpa16(saddr(&Vs[(ns * 64 + row) * 72 + lc4]),
                      &Vp[((jt + 1) * 64 + row) * 64 + lc4]);
            }
            cpa_commit();
            cpa_wait<1>();
        } else {
            cpa_wait<0>();
        }
        __syncthreads();

        const uint32_t* Kst = Ks + st * 64 * 68;
        const uint32_t* Vst = Vs + st * 64 * 72;

        // ---- S = Q @ K^T : 16x64, k=64 (pure LDS + MMA) ----
        float s[8][4];
#pragma unroll
        for (int i = 0; i < 8; i++)
#pragma unroll
            for (int q = 0; q < 4; q++) s[i][q] = 0.f;

#pragma unroll
        for (int kk = 0; kk < 8; kk++) {
            uint32_t a[4];
            a[0] = Qs[(mr + g    ) * 68 + kk * 8 + tg    ];
            a[1] = Qs[(mr + g + 8) * 68 + kk * 8 + tg    ];
            a[2] = Qs[(mr + g    ) * 68 + kk * 8 + tg + 4];
            a[3] = Qs[(mr + g + 8) * 68 + kk * 8 + tg + 4];
#pragma unroll
            for (int ni = 0; ni < 8; ni++) {
                uint32_t b0 = Kst[(ni * 8 + g) * 68 + kk * 8 + tg    ];
                uint32_t b1 = Kst[(ni * 8 + g) * 68 + kk * 8 + tg + 4];
                mma8(s[ni], a, b0, b1);
            }
        }

        // ---- online softmax ----
        float mx0 = -1e30f, mx1 = -1e30f;
#pragma unroll
        for (int ni = 0; ni < 8; ni++) {
            mx0 = fmaxf(mx0, fmaxf(s[ni][0], s[ni][1]));
            mx1 = fmaxf(mx1, fmaxf(s[ni][2], s[ni][3]));
        }
#pragma unroll
        for (int off = 1; off < 4; off <<= 1) {
            mx0 = fmaxf(mx0, __shfl_xor_sync(0xffffffffu, mx0, off));
            mx1 = fmaxf(mx1, __shfl_xor_sync(0xffffffffu, mx1, off));
        }
        float mn0 = fmaxf(m_i[0], mx0);
        float mn1 = fmaxf(m_i[1], mx1);
        float al0 = __expf(m_i[0] - mn0);
        float al1 = __expf(m_i[1] - mn1);
        l_i[0] *= al0; l_i[1] *= al1;
#pragma unroll
        for (int ni = 0; ni < 8; ni++) {
            o[ni][0] *= al0; o[ni][1] *= al0;
            o[ni][2] *= al1; o[ni][3] *= al1;
        }
        float rs0 = 0.f, rs1 = 0.f;
#pragma unroll
        for (int ni = 0; ni < 8; ni++) {
            s[ni][0] = __expf(s[ni][0] - mn0);
            s[ni][1] = __expf(s[ni][1] - mn0);
            s[ni][2] = __expf(s[ni][2] - mn1);
            s[ni][3] = __expf(s[ni][3] - mn1);
            rs0 += s[ni][0] + s[ni][1];
            rs1 += s[ni][2] + s[ni][3];
        }
#pragma unroll
        for (int off = 1; off < 4; off <<= 1) {
            rs0 += __shfl_xor_sync(0xffffffffu, rs0, off);
            rs1 += __shfl_xor_sync(0xffffffffu, rs1, off);
        }
        l_i[0] += rs0; l_i[1] += rs1;
        m_i[0] = mn0;  m_i[1] = mn1;

        // ---- P -> smem as tf32 bits (C-layout to A-layout fixup) ----
#pragma unroll
        for (int ni = 0; ni < 8; ni++) {
            Pw[(g    ) * 68 + ni * 8 + tg * 2    ] = f2tf(s[ni][0]);
            Pw[(g    ) * 68 + ni * 8 + tg * 2 + 1] = f2tf(s[ni][1]);
            Pw[(g + 8) * 68 + ni * 8 + tg * 2    ] = f2tf(s[ni][2]);
            Pw[(g + 8) * 68 + ni * 8 + tg * 2 + 1] = f2tf(s[ni][3]);
        }
        __syncwarp();

        // ---- O += P @ V : 16x64, k=64 (pure LDS + MMA) ----
#pragma unroll
        for (int kk = 0; kk < 8; kk++) {
            uint32_t a[4];
            a[0] = Pw[(g    ) * 68 + kk * 8 + tg    ];
            a[1] = Pw[(g + 8) * 68 + kk * 8 + tg    ];
            a[2] = Pw[(g    ) * 68 + kk * 8 + tg + 4];
            a[3] = Pw[(g + 8) * 68 + kk * 8 + tg + 4];
#pragma unroll
            for (int ni = 0; ni < 8; ni++) {
                uint32_t b0 = Vst[(kk * 8 + tg    ) * 72 + ni * 8 + g];
                uint32_t b1 = Vst[(kk * 8 + tg + 4) * 72 + ni * 8 + g];
                mma8(o[ni], a, b0, b1);
            }
        }
        __syncwarp();
        __syncthreads();   // protect stage st before next prefetch overwrites it
    }

    // ---- epilogue: normalize and write [B, N, INNER] ----
    float inv0 = 1.f / l_i[0];
    float inv1 = 1.f / l_i[1];
    int b = bh >> 4, h = bh & 15;
#pragma unroll
    for (int ni = 0; ni < 8; ni++) {
#pragma unroll
        for (int q = 0; q < 4; q++) {
            int nrow = qt * 64 + w * 16 + g + ((q >= 2) ? 8 : 0);
            int col  = h * 64 + ni * 8 + tg * 2 + (q & 1);
            float v  = o[ni][q] * ((q >= 2) ? inv1 : inv0);
            g_AO[((size_t)(b * Nn + nrow)) * INNER + col] = v;
        }
    }
}

// ============================================================================
extern "C" void kernel_launch(void* const* d_in, const int* in_sizes, int n_in,
                              void* d_out, int out_size)
{
    const float* x    = (const float*)d_in[0];   // [4,2048,1024]
    const float* wqkv = (const float*)d_in[1];   // [1024,3072]
    const float* wout = (const float*)d_in[2];   // [1024,1024]
    const float* bout = (const float*)d_in[3];   // [1024]
    float* out = (float*)d_out;                  // [4,2048,1024]

    // 1) QKV projection with head scatter (+tf32 pre-round, Q pre-scale)
    gemm_k<0><<<dim3(3072 / 128, MROWS / 128), 256>>>(
        x, wqkv, MROWS, 3072, 1024, nullptr, nullptr);

    // 2) flash attention
    cudaFuncSetAttribute(attn_k, cudaFuncAttributeMaxDynamicSharedMemorySize,
                         ATTN_SMEM_BYTES);
    attn_k<<<dim3(Nn / 64, Bb * HEADS), 128, ATTN_SMEM_BYTES>>>();

    // 3) output projection + bias
    gemm_k<1><<<dim3(1024 / 128, MROWS / 128), 256>>>(
        nullptr, wout, MROWS, 1024, 1024, bout, out);
}

// round 11
// speedup vs baseline: 1.2316x; 1.1169x over previous
#include <cuda_runtime.h>
#include <cstdint>

#define DEVI __device__ __forceinline__

namespace {
constexpr int Bb = 4, Nn = 2048, HEADS = 16, DH = 64, INNER = 1024;
constexpr int MROWS = Bb * Nn;                       // 8192
// gemm smem (uint32 words)
constexpr int GA_STG = 256 * 20;                     // A stage: 256 rows x (16+4)
constexpr int GB_STG = 128 * 20;                     // B stage: 128 rows x (16+4)
constexpr int GEMM_SMEM_BYTES = (3 * GA_STG + 3 * GB_STG) * 4;   // 92160
// attn smem (uint32 words)
constexpr int AQ = 128 * 68, AK = 64 * 68, AV = 64 * 68, AP = 16 * 68;
constexpr int ATTN_SMEM_BYTES = (AQ + 2 * AK + 2 * AV + 8 * AP) * 4; // 139264
}

// ---- scratch (device globals: allocation-free) ----
// all hold tf32-rounded bit patterns stored as float (except bias path)
__device__ float g_X    [(size_t)MROWS * 1024];
__device__ float g_WqkvT[(size_t)3072 * 1024];       // [N][K]
__device__ float g_WoutT[(size_t)1024 * 1024];       // [N][K]
__device__ float g_Q    [(size_t)Bb * HEADS * Nn * DH];   // [bh][n][d], pre-scaled 0.125
__device__ float g_K    [(size_t)Bb * HEADS * Nn * DH];   // [bh][n][d]
__device__ float g_V    [(size_t)Bb * HEADS * DH * Nn];   // [bh][d][n]  (TRANSPOSED)
__device__ float g_AO   [(size_t)MROWS * INNER];

DEVI uint32_t f2tf(float x) {
    uint32_t r;
    asm("cvt.rna.tf32.f32 %0, %1;" : "=r"(r) : "f"(x));
    return r;
}

DEVI void mma8(float* c, const uint32_t* a, uint32_t b0, uint32_t b1) {
    asm volatile(
        "mma.sync.aligned.m16n8k8.row.col.f32.tf32.tf32.f32 "
        "{%0,%1,%2,%3}, {%4,%5,%6,%7}, {%8,%9}, {%0,%1,%2,%3};\n"
        : "+f"(c[0]), "+f"(c[1]), "+f"(c[2]), "+f"(c[3])
        : "r"(a[0]), "r"(a[1]), "r"(a[2]), "r"(a[3]), "r"(b0), "r"(b1));
}

DEVI uint32_t saddr(const void* p) {
    return (uint32_t)__cvta_generic_to_shared(p);
}
DEVI void cpa16(uint32_t dst, const void* src) {
    asm volatile("cp.async.cg.shared.global [%0], [%1], 16;\n" :: "r"(dst), "l"(src));
}
DEVI void cpa_commit() { asm volatile("cp.async.commit_group;\n"); }
template <int N> DEVI void cpa_wait() {
    asm volatile("cp.async.wait_group %0;\n" :: "n"(N));
}
// ldmatrix x4 on fp32 data: each 8x8 b16 matrix == an 8x4 fp32 tile.
DEVI void ldsm4(uint32_t* r, uint32_t addr) {
    asm volatile("ldmatrix.sync.aligned.m8n8.x4.shared.b16 {%0,%1,%2,%3}, [%4];"
                 : "=r"(r[0]), "=r"(r[1]), "=r"(r[2]), "=r"(r[3]) : "r"(addr));
}

// ============================================================================
// pre-pass kernels: convert (and transpose) to tf32 bits
// ============================================================================
__global__ void conv_x_k(const float4* __restrict__ in) {
    size_t i = (size_t)blockIdx.x * 256 + threadIdx.x;   // n4 = 2097152
    float4 v = in[i];
    uint4* out = reinterpret_cast<uint4*>(g_X);
    out[i] = make_uint4(f2tf(v.x), f2tf(v.y), f2tf(v.z), f2tf(v.w));
}

template <int DST>   // 0: wqkv -> g_WqkvT, 1: wout -> g_WoutT
__global__ void trans_conv_k(const float* __restrict__ in, int R, int C) {
    __shared__ float t[32][33];
    float* out = (DST == 0) ? g_WqkvT : g_WoutT;
    int bx = blockIdx.x * 32, by = blockIdx.y * 32;
    int tx = threadIdx.x, ty = threadIdx.y;              // block (32, 8)
#pragma unroll
    for (int i = 0; i < 4; i++)
        t[ty + i * 8][tx] = in[(size_t)(by + ty + i * 8) * C + bx + tx];
    __syncthreads();
#pragma unroll
    for (int i = 0; i < 4; i++)
        out[(size_t)(bx + ty + i * 8) * R + by + tx] =
            __uint_as_float(f2tf(t[tx][ty + i * 8]));
}

// ============================================================================
// GEMM: C[M,N] = A[M,K] @ Wt[N,K]^T, all tf32 bits in gmem, fp32 accum.
// Block 256x128, 8 warps (4x2), warp tile 64x64, 3-stage cp.async, ldmatrix.
// MODE 0: A=g_X, W=g_WqkvT, epilogue scatters Q(*0.125)/K/V(transposed) tf32
// MODE 1: A=g_AO, W=g_WoutT, epilogue writes dout + bias (fp32)
// ============================================================================
template <int MODE>
__global__ void __launch_bounds__(256, 1)
gemm_k(int M, int N, int K, const float* __restrict__ bias, float* __restrict__ dout)
{
    extern __shared__ uint32_t sm[];
    const float* Ap = (MODE == 0) ? g_X : g_AO;
    const float* Wt = (MODE == 0) ? g_WqkvT : g_WoutT;

    const int tid = threadIdx.x, lane = tid & 31, wid = tid >> 5;
    const int g = lane >> 2, tg = lane & 3;
    const int wm = wid >> 1, wn = wid & 1;               // 4 x 2 warp grid
    const int bm = blockIdx.y * 256, bn = blockIdx.x * 128;
    const uint32_t smb = saddr(sm);

    // cp.async per-thread coords
    const int crow = tid >> 2, cc = (tid & 3) << 2;      // chunk col (floats)

    // ldmatrix per-lane offsets
    const int sel = lane >> 3, lr = lane & 7;
    const int a_ro = lr + ((sel & 1) << 3), a_co = (sel & 2) << 1;   // +8 row / +4 col
    const int b_ro = lr + ((sel & 2) << 2), b_co = (sel & 1) << 2;
    const uint32_t a_base = (uint32_t)((wm * 64 + a_ro) * 20 + a_co);
    const uint32_t b_base = (uint32_t)((wn * 64 + b_ro) * 20 + b_co);

    float acc[4][8][4];
#pragma unroll
    for (int mi = 0; mi < 4; mi++)
#pragma unroll
        for (int ni = 0; ni < 8; ni++)
#pragma unroll
            for (int q = 0; q < 4; q++) acc[mi][ni][q] = 0.f;

    auto issue = [&](int s, int kt) {
#pragma unroll
        for (int i = 0; i < 4; i++) {                    // A: 256 rows
            int r = crow + i * 64;
            cpa16(smb + (uint32_t)(s * GA_STG + r * 20 + cc) * 4,
                  &Ap[(size_t)(bm + r) * K + kt * 16 + cc]);
        }
#pragma unroll
        for (int i = 0; i < 2; i++) {                    // B: 128 rows [n][k]
            int r = crow + i * 64;
            cpa16(smb + (uint32_t)(3 * GA_STG + s * GB_STG + r * 20 + cc) * 4,
                  &Wt[(size_t)(bn + r) * K + kt * 16 + cc]);
        }
    };

    const int nkt = K >> 4;
    issue(0, 0); cpa_commit();
    issue(1, 1); cpa_commit();

    for (int kt = 0; kt < nkt; kt++) {
        if (kt + 2 < nkt) issue((kt + 2) % 3, kt + 2);
        cpa_commit();                                    // always commit: group math stays aligned
        cpa_wait<2>();
        __syncthreads();

        const int s = kt % 3;
        const uint32_t As0 = smb + (uint32_t)(s * GA_STG) * 4;
        const uint32_t Bs0 = smb + (uint32_t)(3 * GA_STG + s * GB_STG) * 4;

#pragma unroll
        for (int kk = 0; kk < 16; kk += 8) {
            uint32_t af[4][4], bf[4][4];
#pragma unroll
            for (int mi = 0; mi < 4; mi++)
                ldsm4(af[mi], As0 + (a_base + (uint32_t)(mi * 16 * 20 + kk)) * 4);
#pragma unroll
            for (int j = 0; j < 4; j++)
                ldsm4(bf[j], Bs0 + (b_base + (uint32_t)(j * 16 * 20 + kk)) * 4);
#pragma unroll
            for (int mi = 0; mi < 4; mi++)
#pragma unroll
                for (int ni = 0; ni < 8; ni++)
                    mma8(acc[mi][ni], af[mi],
                         bf[ni >> 1][(ni & 1) << 1], bf[ni >> 1][((ni & 1) << 1) + 1]);
        }
        __syncthreads();                                 // protect stage s before reuse
    }

    // epilogue
#pragma unroll
    for (int mi = 0; mi < 4; mi++) {
#pragma unroll
        for (int ni = 0; ni < 8; ni++) {
#pragma unroll
            for (int q = 0; q < 4; q++) {
                int r = bm + wm * 64 + mi * 16 + g + ((q >= 2) ? 8 : 0);
                int c = bn + wn * 64 + ni * 8 + tg * 2 + (q & 1);
                float v = acc[mi][ni][q];
                if (MODE == 0) {
                    int b = r >> 11, n = r & 2047;
                    int which = c >> 10, cc2 = c & 1023;
                    int h = cc2 >> 6, d = cc2 & 63;
                    size_t bh = (size_t)b * HEADS + h;
                    if (which == 0) {
                        g_Q[(bh * Nn + n) * DH + d] = __uint_as_float(f2tf(v * 0.125f));
                    } else if (which == 1) {
                        g_K[(bh * Nn + n) * DH + d] = __uint_as_float(f2tf(v));
                    } else {
                        g_V[(bh * DH + d) * Nn + n] = __uint_as_float(f2tf(v)); // transposed
                    }
                } else {
                    dout[(size_t)r * N + c] = v + bias[c];
                }
            }
        }
    }
}

// ============================================================================
// Flash attention: block = one (b,h) x 128 query rows, 8 warps x 16 rows.
// Bc = 64, double-buffered K/V cp.async, ldmatrix fragments everywhere.
// ============================================================================
__global__ void __launch_bounds__(256, 1)
attn_k()
{
    extern __shared__ uint32_t smu[];
    uint32_t* Qs = smu;                      // [128][68]
    uint32_t* Ks = Qs + AQ;                  // [2][64][68]  rows=j, cols=d
    uint32_t* Vs = Ks + 2 * AK;              // [2][64][68]  rows=d, cols=j (transposed)
    uint32_t* Ps = Vs + 2 * AV;              // [8][16][68]

    const int tid = threadIdx.x, lane = tid & 31, w = tid >> 5;
    const int g = lane >> 2, tg = lane & 3;
    const int bh = blockIdx.y, qt = blockIdx.x;   // qt 0..15

    const size_t basek = (size_t)bh * Nn * DH;
    const float* Qp = g_Q + basek + (size_t)qt * 128 * DH;
    const float* Kp = g_K + basek;
    const float* Vp = g_V + (size_t)bh * DH * Nn;
    const uint32_t smb = saddr(smu);

    const int lrow = tid >> 4, lc4 = (tid & 15) << 2;    // 64-float rows, 16B chunks

    // ldmatrix per-lane offsets
    const int sel = lane >> 3, lr = lane & 7;
    const int a_ro = lr + ((sel & 1) << 3), a_co = (sel & 2) << 1;
    const int b_ro = lr + ((sel & 2) << 2), b_co = (sel & 1) << 2;
    const uint32_t Qaddr = smb + (uint32_t)((w * 16 + a_ro) * 68 + a_co) * 4;
    const uint32_t Paddr = smb + (uint32_t)(AQ + 2 * AK + 2 * AV +
                                            (w * 16 + a_ro) * 68 + a_co) * 4;
    const uint32_t kb_base = (uint32_t)(b_ro * 68 + b_co);
    const uint32_t Ks_u = smb + (uint32_t)AQ * 4;
    const uint32_t Vs_u = smb + (uint32_t)(AQ + 2 * AK) * 4;

    // prologue: Q + K0 + V0 in group 0
#pragma unroll
    for (int i = 0; i < 4; i++) {
        int r = lrow + i * 16;                           // 0..63
        cpa16(Ks_u + (uint32_t)(r * 68 + lc4) * 4, &Kp[r * 64 + lc4]);
        cpa16(Vs_u + (uint32_t)(r * 68 + lc4) * 4, &Vp[(size_t)r * Nn + lc4]);
    }
#pragma unroll
    for (int i = 0; i < 8; i++) {
        int r = lrow + i * 16;                           // 0..127
        cpa16(smb + (uint32_t)(r * 68 + lc4) * 4, &Qp[r * 64 + lc4]);
    }
    cpa_commit();

    float m_i[2] = {-1e30f, -1e30f};
    float l_i[2] = {0.f, 0.f};
    float o[8][4];
#pragma unroll
    for (int i = 0; i < 8; i++)
#pragma unroll
        for (int q = 0; q < 4; q++) o[i][q] = 0.f;

    uint32_t* Pw = Ps + w * 16 * 68;

    for (int jt = 0; jt < 32; jt++) {
        const int st = jt & 1;
        if (jt + 1 < 32) {
            const int ns = st ^ 1;
#pragma unroll
            for (int i = 0; i < 4; i++) {
                int r = lrow + i * 16;
                cpa16(Ks_u + (uint32_t)((ns * 64 + r) * 68 + lc4) * 4,
                      &Kp[((jt + 1) * 64 + r) * 64 + lc4]);
                cpa16(Vs_u + (uint32_t)((ns * 64 + r) * 68 + lc4) * 4,
                      &Vp[(size_t)r * Nn + (jt + 1) * 64 + lc4]);
            }
        }
        cpa_commit();
        cpa_wait<1>();
        __syncthreads();

        const uint32_t Kst = Ks_u + (uint32_t)(st * AK) * 4;
        const uint32_t Vst = Vs_u + (uint32_t)(st * AV) * 4;

        // ---- S = Q @ K^T : 16x64, k=64 ----
        float s[8][4];
#pragma unroll
        for (int i = 0; i < 8; i++)
#pragma unroll
            for (int q = 0; q < 4; q++) s[i][q] = 0.f;

#pragma unroll
        for (int kk = 0; kk < 64; kk += 8) {
            uint32_t a[4], bf[4][4];
            ldsm4(a, Qaddr + (uint32_t)kk * 4);
#pragma unroll
            for (int j = 0; j < 4; j++)
                ldsm4(bf[j], Kst + (kb_base + (uint32_t)(j * 16 * 68 + kk)) * 4);
#pragma unroll
            for (int ni = 0; ni < 8; ni++)
                mma8(s[ni], a, bf[ni >> 1][(ni & 1) << 1], bf[ni >> 1][((ni & 1) << 1) + 1]);
        }

        // ---- online softmax ----
        float mx0 = -1e30f, mx1 = -1e30f;
#pragma unroll
        for (int ni = 0; ni < 8; ni++) {
            mx0 = fmaxf(mx0, fmaxf(s[ni][0], s[ni][1]));
            mx1 = fmaxf(mx1, fmaxf(s[ni][2], s[ni][3]));
        }
#pragma unroll
        for (int off = 1; off < 4; off <<= 1) {
            mx0 = fmaxf(mx0, __shfl_xor_sync(0xffffffffu, mx0, off));
            mx1 = fmaxf(mx1, __shfl_xor_sync(0xffffffffu, mx1, off));
        }
        float mn0 = fmaxf(m_i[0], mx0);
        float mn1 = fmaxf(m_i[1], mx1);
        float al0 = __expf(m_i[0] - mn0);
        float al1 = __expf(m_i[1] - mn1);
        l_i[0] *= al0; l_i[1] *= al1;
#pragma unroll
        for (int ni = 0; ni < 8; ni++) {
            o[ni][0] *= al0; o[ni][1] *= al0;
            o[ni][2] *= al1; o[ni][3] *= al1;
        }
        float rs0 = 0.f, rs1 = 0.f;
#pragma unroll
        for (int ni = 0; ni < 8; ni++) {
            s[ni][0] = __expf(s[ni][0] - mn0);
            s[ni][1] = __expf(s[ni][1] - mn0);
            s[ni][2] = __expf(s[ni][2] - mn1);
            s[ni][3] = __expf(s[ni][3] - mn1);
            rs0 += s[ni][0] + s[ni][1];
            rs1 += s[ni][2] + s[ni][3];
        }
#pragma unroll
        for (int off = 1; off < 4; off <<= 1) {
            rs0 += __shfl_xor_sync(0xffffffffu, rs0, off);
            rs1 += __shfl_xor_sync(0xffffffffu, rs1, off);
        }
        l_i[0] += rs0; l_i[1] += rs1;
        m_i[0] = mn0;  m_i[1] = mn1;

        // ---- P -> per-warp smem as tf32 bits ----
#pragma unroll
        for (int ni = 0; ni < 8; ni++) {
            Pw[(g    ) * 68 + ni * 8 + tg * 2    ] = f2tf(s[ni][0]);
            Pw[(g    ) * 68 + ni * 8 + tg * 2 + 1] = f2tf(s[ni][1]);
            Pw[(g + 8) * 68 + ni * 8 + tg * 2    ] = f2tf(s[ni][2]);
            Pw[(g + 8) * 68 + ni * 8 + tg * 2 + 1] = f2tf(s[ni][3]);
        }
        __syncwarp();

        // ---- O += P @ V : 16x64, k=64 ----
#pragma unroll
        for (int kk = 0; kk < 64; kk += 8) {
            uint32_t a[4], bf[4][4];
            ldsm4(a, Paddr + (uint32_t)kk * 4);
#pragma unroll
            for (int j = 0; j < 4; j++)
                ldsm4(bf[j], Vst + (kb_base + (uint32_t)(j * 16 * 68 + kk)) * 4);
#pragma unroll
            for (int ni = 0; ni < 8; ni++)
                mma8(o[ni], a, bf[ni >> 1][(ni & 1) << 1], bf[ni >> 1][((ni & 1) << 1) + 1]);
        }
        __syncthreads();     // stage st is overwritten by next iteration's issue
    }

    // ---- epilogue: normalize, tf32-round, write [B, N, INNER] ----
    float inv0 = 1.f / l_i[0];
    float inv1 = 1.f / l_i[1];
    int b = bh >> 4, h = bh & 15;
#pragma unroll
    for (int ni = 0; ni < 8; ni++) {
#pragma unroll
        for (int q = 0; q < 4; q++) {
            int nrow = qt * 128 + w * 16 + g + ((q >= 2) ? 8 : 0);
            int col  = h * 64 + ni * 8 + tg * 2 + (q & 1);
            float v  = o[ni][q] * ((q >= 2) ? inv1 : inv0);
            g_AO[((size_t)(b * Nn + nrow)) * INNER + col] = __uint_as_float(f2tf(v));
        }
    }
}

// ============================================================================
extern "C" void kernel_launch(void* const* d_in, const int* in_sizes, int n_in,
                              void* d_out, int out_size)
{
    const float* x    = (const float*)d_in[0];   // [4,2048,1024]
    const float* wqkv = (const float*)d_in[1];   // [1024,3072]
    const float* wout = (const float*)d_in[2];   // [1024,1024]
    const float* bout = (const float*)d_in[3];   // [1024]
    float* out = (float*)d_out;                  // [4,2048,1024]

    // 0) pre-convert to tf32 bits (+ weight transposes)
    conv_x_k<<<(MROWS * 1024 / 4) / 256, 256>>>((const float4*)x);
    trans_conv_k<0><<<dim3(3072 / 32, 1024 / 32), dim3(32, 8)>>>(wqkv, 1024, 3072);
    trans_conv_k<1><<<dim3(1024 / 32, 1024 / 32), dim3(32, 8)>>>(wout, 1024, 1024);

    // 1) QKV projection with head scatter (Q pre-scale, V pre-transpose)
    cudaFuncSetAttribute(gemm_k<0>, cudaFuncAttributeMaxDynamicSharedMemorySize,
                         GEMM_SMEM_BYTES);
    gemm_k<0><<<dim3(3072 / 128, MROWS / 256), 256, GEMM_SMEM_BYTES>>>(
        MROWS, 3072, 1024, nullptr, nullptr);

    // 2) flash attention (Br=128, 8 warps)
    cudaFuncSetAttribute(attn_k, cudaFuncAttributeMaxDynamicSharedMemorySize,
                         ATTN_SMEM_BYTES);
    attn_k<<<dim3(Nn / 128, Bb * HEADS), 256, ATTN_SMEM_BYTES>>>();

    // 3) output projection + bias
    cudaFuncSetAttribute(gemm_k<1>, cudaFuncAttributeMaxDynamicSharedMemorySize,
                         GEMM_SMEM_BYTES);
    gemm_k<1><<<dim3(1024 / 128, MROWS / 256), 256, GEMM_SMEM_BYTES>>>(
        MROWS, 1024, 1024, bout, out);
}